// round 14
// baseline (speedup 1.0000x reference)
#include <cuda_runtime.h>
#include <cuda_fp16.h>
#include <cuda_bf16.h>
#include <cstdint>

#define H 4
#define MAXN 100000
#define MAXE 1000000
#define NEG 0.2f
#define EPSF 1e-16f
#define SCAN_NB ((MAXN + 255) / 256)

// ---------------- scratch (device globals; no allocation allowed) ----------------
__device__ __align__(16) __half g_h1h[MAXN * 128];          // layer1 features fp16
__device__ __align__(16) __half g_h2h[MAXN * 64];           // layer2 features fp16
__device__ __align__(16) __nv_bfloat16 g_w1thi[128 * 128];  // W1^T split [n][k]
__device__ __align__(16) __nv_bfloat16 g_w1tlo[128 * 128];
__device__ __align__(16) float g_as1[MAXN * H];
__device__ __align__(16) float g_ad1[MAXN * H];
__device__ __align__(16) float g_as2[MAXN * H];
__device__ __align__(16) float g_ad2[MAXN * H];
__device__ int g_src[MAXE];
__device__ int g_dst[MAXE];
__device__ int g_csr_src[MAXE];
__device__ int g_deg[MAXN];
__device__ int g_rowptr[MAXN + 1];
__device__ int g_wpos[MAXN];
__device__ int g_bsum[SCAN_NB];
__device__ int g_is64;

// ---------------- prep: dtype sniff + zero deg + convert W1 ----------------
__global__ void prep_kernel(const int* __restrict__ ei_raw,
                            const float* __restrict__ W1, int N) {
    int gt = blockIdx.x * blockDim.x + threadIdx.x;
    if (gt == 0) {
        int all0 = 1;
        for (int i = 0; i < 32; i++)
            if (ei_raw[2 * i + 1] != 0) { all0 = 0; break; }
        g_is64 = all0;
    }
    if (gt < N) g_deg[gt] = 0;
    if (gt < 128 * 128) {
        int k = gt >> 7, n = gt & 127;
        float a = W1[k * 128 + n];
        __nv_bfloat16 hv = __float2bfloat16(a);
        g_w1thi[n * 128 + k] = hv;
        g_w1tlo[n * 128 + k] = __float2bfloat16(a - __bfloat162float(hv));
    }
}

// ---------------- decode + degree count fused ----------------
__global__ void decode_count_kernel(const void* __restrict__ ei, int E, int N) {
    int e = blockIdx.x * blockDim.x + threadIdx.x;
    if (e >= E) return;
    int s, d;
    if (g_is64) {
        s = (int)((const long long*)ei)[e];
        d = (int)((const long long*)ei)[E + e];
    } else {
        s = ((const int*)ei)[e];
        d = ((const int*)ei)[E + e];
    }
    s = s < 0 ? 0 : (s >= N ? N - 1 : s);
    d = d < 0 ? 0 : (d >= N ? N - 1 : d);
    g_src[e] = s;
    g_dst[e] = d;
    atomicAdd(&g_deg[d], 1);
}

// ---------------- scan part 1: per-block exclusive scan + block sums ----------------
__global__ void scan1_kernel(int N) {
    __shared__ int s[256];
    int t = threadIdx.x;
    int i = blockIdx.x * 256 + t;
    int v = (i < N) ? g_deg[i] : 0;
    s[t] = v;
    for (int off = 1; off < 256; off <<= 1) {
        __syncthreads();
        int tv = (t >= off) ? s[t - off] : 0;
        __syncthreads();
        s[t] += tv;
    }
    __syncthreads();
    if (i < N) g_rowptr[i] = s[t] - v;
    if (t == 255) g_bsum[blockIdx.x] = s[255];
}

// ---------------- scan part 2: add prefix of block sums ----------------
__global__ void scan3_kernel(int N, int E, int nb) {
    __shared__ int red[256];
    int t = threadIdx.x;
    int blk = blockIdx.x;
    int part = 0;
    for (int i = t; i < blk; i += 256) part += g_bsum[i];
    red[t] = part;
    __syncthreads();
    for (int off = 128; off > 0; off >>= 1) {
        if (t < off) red[t] += red[t + off];
        __syncthreads();
    }
    int offv = red[0];
    int i = blk * 256 + t;
    if (i < N) {
        int r = g_rowptr[i] + offv;
        g_rowptr[i] = r;
        g_wpos[i] = r;
    }
    if (i == 0) g_rowptr[N] = E;
}

__global__ void scatter_kernel(int E) {
    int e = blockIdx.x * blockDim.x + threadIdx.x;
    if (e >= E) return;
    int d = g_dst[e];
    int p = atomicAdd(&g_wpos[d], 1);
    g_csr_src[p] = g_src[e];
}

// ---------------- bf16 mma helper ----------------
__device__ __forceinline__ void mma_bf16(float* c, uint32_t a0, uint32_t a1,
                                         uint32_t a2, uint32_t a3,
                                         uint32_t b0, uint32_t b1) {
    asm volatile(
        "mma.sync.aligned.m16n8k16.row.col.f32.bf16.bf16.f32 "
        "{%0,%1,%2,%3}, {%4,%5,%6,%7}, {%8,%9}, {%0,%1,%2,%3};\n"
        : "+f"(c[0]), "+f"(c[1]), "+f"(c[2]), "+f"(c[3])
        : "r"(a0), "r"(a1), "r"(a2), "r"(a3), "r"(b0), "r"(b1));
}

__device__ __forceinline__ uint32_t pack_hi2(float a, float b) {
    __nv_bfloat162 p = __floats2bfloat162_rn(a, b);
    return *(uint32_t*)&p;
}

// ---------------- GEMM1 (tensor): h1h[N,128] = x[N,128] @ W1 via bf16x3; x split fused ----------------
__global__ __launch_bounds__(256) void gemm1_tc_kernel(const float* __restrict__ x, int N) {
    __shared__ uint32_t As[2][128][8];  // [part][row][kpair]
    __shared__ uint32_t Bs[2][128][8];  // [part][n][kpair]
    int tid = threadIdx.x;
    int lane = tid & 31, wid = tid >> 5;
    int gid = lane >> 2, tig = lane & 3;
    int wm = (wid >> 1) * 32, wn = (wid & 1) * 64;
    int rowbase = blockIdx.x * 128;
    float c[2][8][4];
#pragma unroll
    for (int mt = 0; mt < 2; mt++)
#pragma unroll
        for (int nt = 0; nt < 8; nt++)
#pragma unroll
            for (int r = 0; r < 4; r++) c[mt][nt][r] = 0.f;

    for (int k0 = 0; k0 < 128; k0 += 16) {
        {   // A tile: load fp32 x, split to hi/lo in regs, store both parts
            int row = tid >> 1, hf = (tid & 1) * 4;  // 8 floats per thread
            int grow = rowbase + row;
            float4 v0 = make_float4(0.f, 0.f, 0.f, 0.f), v1 = v0;
            if (grow < N) {
                const float* p = &x[grow * 128 + k0 + hf * 2];
                v0 = *(const float4*)p;
                v1 = *(const float4*)(p + 4);
            }
            float f[8] = {v0.x, v0.y, v0.z, v0.w, v1.x, v1.y, v1.z, v1.w};
            uint32_t hi[4], lo[4];
#pragma unroll
            for (int q = 0; q < 4; q++) {
                float a = f[2 * q], b = f[2 * q + 1];
                float ha = __bfloat162float(__float2bfloat16(a));
                float hb = __bfloat162float(__float2bfloat16(b));
                hi[q] = pack_hi2(a, b);
                lo[q] = pack_hi2(a - ha, b - hb);
            }
            *(uint4*)&As[0][row][hf] = make_uint4(hi[0], hi[1], hi[2], hi[3]);
            *(uint4*)&As[1][row][hf] = make_uint4(lo[0], lo[1], lo[2], lo[3]);
        }
#pragma unroll
        for (int i = 0; i < 2; i++) {  // B tile
            int cc = tid + i * 256;
            int part = cc >> 8, rem = cc & 255;
            int n = rem >> 1, hf = (rem & 1) * 4;
            const __nv_bfloat16* sp = part ? g_w1tlo : g_w1thi;
            *(uint4*)&Bs[part][n][hf] = *(const uint4*)&sp[n * 128 + k0 + hf * 2];
        }
        __syncthreads();
        uint32_t af[2][2][4];
#pragma unroll
        for (int p = 0; p < 2; p++)
#pragma unroll
            for (int mt = 0; mt < 2; mt++) {
                int r = wm + mt * 16 + gid;
                af[p][mt][0] = As[p][r][tig];
                af[p][mt][1] = As[p][r + 8][tig];
                af[p][mt][2] = As[p][r][tig + 4];
                af[p][mt][3] = As[p][r + 8][tig + 4];
            }
#pragma unroll
        for (int combo = 0; combo < 3; combo++) {
            int pa = (combo == 2) ? 1 : 0;
            int pb = (combo == 1) ? 1 : 0;
#pragma unroll
            for (int nt = 0; nt < 8; nt++) {
                int nr = wn + nt * 8 + gid;
                uint32_t b0 = Bs[pb][nr][tig];
                uint32_t b1 = Bs[pb][nr][tig + 4];
                mma_bf16(c[0][nt], af[pa][0][0], af[pa][0][1], af[pa][0][2], af[pa][0][3], b0, b1);
                mma_bf16(c[1][nt], af[pa][1][0], af[pa][1][1], af[pa][1][2], af[pa][1][3], b0, b1);
            }
        }
        __syncthreads();
    }
#pragma unroll
    for (int mt = 0; mt < 2; mt++)
#pragma unroll
        for (int nt = 0; nt < 8; nt++) {
            int row = rowbase + wm + mt * 16 + gid;
            int col = wn + nt * 8 + tig * 2;
            if (row < N)
                *(__half2*)&g_h1h[row * 128 + col] = __floats2half2_rn(c[mt][nt][0], c[mt][nt][1]);
            if (row + 8 < N)
                *(__half2*)&g_h1h[(row + 8) * 128 + col] = __floats2half2_rn(c[mt][nt][2], c[mt][nt][3]);
        }
}

// ---------------- attention halves for layer 1 ----------------
__global__ __launch_bounds__(256) void attn1_kernel(const float* __restrict__ a_src,
                                                    const float* __restrict__ a_dst, int N) {
    int i = blockIdx.x * blockDim.x + threadIdx.x;
    if (i >= N * H) return;
    int hh = i & 3;
    const __half* row = g_h1h + (size_t)i * 32;
    const float* av = a_src + hh * 32;
    const float* bv = a_dst + hh * 32;
    float s = 0.f, d = 0.f;
#pragma unroll
    for (int f = 0; f < 32; f += 2) {
        float2 hv = __half22float2(*(const __half2*)&row[f]);
        s += hv.x * av[f] + hv.y * av[f + 1];
        d += hv.x * bv[f] + hv.y * bv[f + 1];
    }
    g_as1[i] = s;
    g_ad1[i] = d;
}

__device__ __forceinline__ void acc8(float* acc, uint4 r, float ex) {
    float2 p0 = __half22float2(*(__half2*)&r.x);
    float2 p1 = __half22float2(*(__half2*)&r.y);
    float2 p2 = __half22float2(*(__half2*)&r.z);
    float2 p3 = __half22float2(*(__half2*)&r.w);
    acc[0] += ex * p0.x; acc[1] += ex * p0.y;
    acc[2] += ex * p1.x; acc[3] += ex * p1.y;
    acc[4] += ex * p2.x; acc[5] += ex * p2.y;
    acc[6] += ex * p3.x; acc[7] += ex * p3.y;
}

// ---------------- gather layer 1 FUSED: 2 edges/warp, 16 lanes x uint4 per row ----------------
__global__ __launch_bounds__(256) void gather1_fused_kernel(const float* __restrict__ b,
                                                            const float* __restrict__ W2,
                                                            const float* __restrict__ a2s,
                                                            const float* __restrict__ a2d,
                                                            int N) {
    __shared__ float2 Ws[32][32];     // W2 as float2: Ws[k][c] = (W2[k][2c], W2[k][2c+1])
    __shared__ float x2buf[8][32];    // per-warp x2 row
    int tid = threadIdx.x;
#pragma unroll
    for (int i = 0; i < 4; i++) {
        int idx = tid + i * 256;          // 0..1023
        int k = idx >> 5, c = idx & 31;
        Ws[k][c] = *(const float2*)&W2[k * 64 + c * 2];
    }
    __syncthreads();

    int gt = blockIdx.x * 256 + tid;
    int d = gt >> 5;
    if (d >= N) return;
    int lane = gt & 31;
    int w = (tid >> 5);
    int sub = lane >> 4;         // edge parity
    int l = lane & 15;           // covers halves l*8 .. l*8+7
    int head = l >> 2;           // (l*8)/32
    int beg = g_rowptr[d], end = g_rowptr[d + 1];
    float adh = g_ad1[d * 4 + head];
    float acc[8] = {0.f, 0.f, 0.f, 0.f, 0.f, 0.f, 0.f, 0.f};
    float dsum = 0.f;
    int j = beg + sub;
    for (; j + 2 < end; j += 4) {   // 2 edges per lane-iteration (j, j+2), 2 subs
        int s0 = g_csr_src[j];
        int s1 = g_csr_src[j + 2];
        float sc0 = g_as1[s0 * 4 + head] + adh;
        float sc1 = g_as1[s1 * 4 + head] + adh;
        uint4 r0 = *(const uint4*)&g_h1h[s0 * 128 + l * 8];
        uint4 r1 = *(const uint4*)&g_h1h[s1 * 128 + l * 8];
        sc0 = sc0 > 0.f ? sc0 : NEG * sc0;
        sc1 = sc1 > 0.f ? sc1 : NEG * sc1;
        float e0 = __expf(sc0), e1 = __expf(sc1);
        acc8(acc, r0, e0);
        acc8(acc, r1, e1);
        dsum += e0 + e1;
    }
    if (j < end) {
        int s = g_csr_src[j];
        float sc = g_as1[s * 4 + head] + adh;
        sc = sc > 0.f ? sc : NEG * sc;
        float ex = __expf(sc);
        uint4 r = *(const uint4*)&g_h1h[s * 128 + l * 8];
        acc8(acc, r, ex);
        dsum += ex;
    }
    // combine the two edge-subgroups
#pragma unroll
    for (int k = 0; k < 8; k++) acc[k] += __shfl_xor_sync(0xffffffffu, acc[k], 16);
    dsum += __shfl_xor_sync(0xffffffffu, dsum, 16);
    float inv = 1.f / (dsum + EPSF);
#pragma unroll
    for (int k = 0; k < 8; k++) acc[k] *= inv;
    // mean over heads: head = bits 2,3 of l
#pragma unroll
    for (int m = 4; m <= 8; m <<= 1)
#pragma unroll
        for (int k = 0; k < 8; k++) acc[k] += __shfl_xor_sync(0xffffffffu, acc[k], m);
    if (lane < 4) {  // features lane*8 .. lane*8+7
        float4 b0 = *(const float4*)&b[lane * 8];
        float4 b1 = *(const float4*)&b[lane * 8 + 4];
        float bb[8] = {b0.x, b0.y, b0.z, b0.w, b1.x, b1.y, b1.z, b1.w};
#pragma unroll
        for (int k = 0; k < 8; k++) {
            float o = 0.25f * acc[k] + bb[k];
            x2buf[w][lane * 8 + k] = o > 0.f ? o : 0.f;
        }
    }
    __syncwarp();
    // gemm2 row: h2[c0], h2[c1] for c0 = lane*2, c1 = lane*2+1
    float h0 = 0.f, h1 = 0.f;
#pragma unroll
    for (int k = 0; k < 32; k++) {
        float xv = x2buf[w][k];      // broadcast
        float2 wv = Ws[k][lane];
        h0 += xv * wv.x;
        h1 += xv * wv.y;
    }
    *(__half2*)&g_h2h[d * 64 + lane * 2] = __floats2half2_rn(h0, h1);
    // attn2
    int c0f = (lane * 2) & 15;
    int h2d = lane >> 3;
    float ps = h0 * a2s[h2d * 16 + c0f] + h1 * a2s[h2d * 16 + c0f + 1];
    float pd = h0 * a2d[h2d * 16 + c0f] + h1 * a2d[h2d * 16 + c0f + 1];
#pragma unroll
    for (int m = 1; m <= 4; m <<= 1) {
        ps += __shfl_xor_sync(0xffffffffu, ps, m);
        pd += __shfl_xor_sync(0xffffffffu, pd, m);
    }
    if ((lane & 7) == 0) {
        g_as2[d * 4 + h2d] = ps;
        g_ad2[d * 4 + h2d] = pd;
    }
}

// ---------------- gather layer 2: 4 edges/warp, 8 lanes x uint4 per row ----------------
__global__ __launch_bounds__(256) void gather2_kernel(const float* __restrict__ b,
                                                      float* __restrict__ out, int N) {
    int gt = blockIdx.x * 256 + threadIdx.x;
    int d = gt >> 5;
    if (d >= N) return;
    int lane = gt & 31;
    int sub = lane >> 3;         // 4 edge subgroups
    int l = lane & 7;            // covers halves l*8 .. l*8+7
    int head = l >> 1;           // (l*8)/16
    int beg = g_rowptr[d], end = g_rowptr[d + 1];
    float adh = g_ad2[d * 4 + head];
    float acc[8] = {0.f, 0.f, 0.f, 0.f, 0.f, 0.f, 0.f, 0.f};
    float dsum = 0.f;
    for (int j = beg + sub; j < end; j += 4) {
        int s = g_csr_src[j];
        float sc = g_as2[s * 4 + head] + adh;
        sc = sc > 0.f ? sc : NEG * sc;
        float ex = __expf(sc);
        uint4 r = *(const uint4*)&g_h2h[s * 64 + l * 8];
        acc8(acc, r, ex);
        dsum += ex;
    }
    // combine the 4 edge subgroups (bits 3,4 of lane)
#pragma unroll
    for (int m = 8; m <= 16; m <<= 1) {
#pragma unroll
        for (int k = 0; k < 8; k++) acc[k] += __shfl_xor_sync(0xffffffffu, acc[k], m);
        dsum += __shfl_xor_sync(0xffffffffu, dsum, m);
    }
    float inv = 1.f / (dsum + EPSF);
#pragma unroll
    for (int k = 0; k < 8; k++) acc[k] *= inv;
    // mean over heads: head = bits 1,2 of l
#pragma unroll
    for (int m = 2; m <= 4; m <<= 1)
#pragma unroll
        for (int k = 0; k < 8; k++) acc[k] += __shfl_xor_sync(0xffffffffu, acc[k], m);
    if (lane < 2) {  // features lane*8 .. lane*8+7
        float4 b0 = *(const float4*)&b[lane * 8];
        float4 b1 = *(const float4*)&b[lane * 8 + 4];
        float4 o0, o1;
        o0.x = 0.25f * acc[0] + b0.x; o0.y = 0.25f * acc[1] + b0.y;
        o0.z = 0.25f * acc[2] + b0.z; o0.w = 0.25f * acc[3] + b0.w;
        o1.x = 0.25f * acc[4] + b1.x; o1.y = 0.25f * acc[5] + b1.y;
        o1.z = 0.25f * acc[6] + b1.z; o1.w = 0.25f * acc[7] + b1.w;
        *(float4*)&out[d * 16 + lane * 8] = o0;
        *(float4*)&out[d * 16 + lane * 8 + 4] = o1;
    }
}

extern "C" void kernel_launch(void* const* d_in, const int* in_sizes, int n_in,
                              void* d_out, int out_size) {
    const float* x = (const float*)d_in[0];
    const void* ei = d_in[1];
    const float* W1 = (const float*)d_in[2];
    const float* a1s = (const float*)d_in[3];
    const float* a1d = (const float*)d_in[4];
    const float* b1 = (const float*)d_in[5];
    const float* W2 = (const float*)d_in[6];
    const float* a2s = (const float*)d_in[7];
    const float* a2d = (const float*)d_in[8];
    const float* b2 = (const float*)d_in[9];
    int N = in_sizes[0] / 128;
    int E = in_sizes[1] / 2;
    if (N > MAXN) N = MAXN;
    if (E > MAXE) E = MAXE;
    float* out = (float*)d_out;
    int nb = (N + 255) / 256;
    int grid_e = (E + 255) / 256;
    int grid_warp = (N * 32 + 255) / 256;
    int grid_g = (N + 127) / 128;

    prep_kernel<<<nb, 256>>>((const int*)ei, W1, N);                 // 1
    decode_count_kernel<<<grid_e, 256>>>(ei, E, N);                  // 2
    scan1_kernel<<<nb, 256>>>(N);                                    // 3
    gemm1_tc_kernel<<<grid_g, 256>>>(x, N);                          // 4  <- ncu samples launch #4
    scan3_kernel<<<nb, 256>>>(N, E, nb);                             // 5
    scatter_kernel<<<grid_e, 256>>>(E);                              // 6
    attn1_kernel<<<(N * 4 + 255) / 256, 256>>>(a1s, a1d, N);         // 7
    gather1_fused_kernel<<<grid_warp, 256>>>(b1, W2, a2s, a2d, N);   // 8
    gather2_kernel<<<grid_warp, 256>>>(b2, out, N);                  // 9
}

// round 15
// speedup vs baseline: 1.3971x; 1.3971x over previous
#include <cuda_runtime.h>
#include <cuda_fp16.h>
#include <cuda_bf16.h>
#include <cstdint>

#define H 4
#define MAXN 100000
#define MAXE 1000000
#define NEG 0.2f
#define EPSF 1e-16f
#define SCAN_NB ((MAXN + 255) / 256)

// ---------------- scratch (device globals; no allocation allowed) ----------------
__device__ __align__(16) __half g_h1h[MAXN * 128];          // layer1 features fp16
__device__ __align__(16) __half g_h2h[MAXN * 64];           // layer2 features fp16
__device__ __align__(16) __nv_bfloat16 g_w1thi[128 * 128];  // W1^T split [n][k]
__device__ __align__(16) __nv_bfloat16 g_w1tlo[128 * 128];
__device__ __align__(16) float g_as1[MAXN * H];
__device__ __align__(16) float g_ad1[MAXN * H];
__device__ __align__(16) float g_as2[MAXN * H];
__device__ __align__(16) float g_ad2[MAXN * H];
__device__ int g_src[MAXE];
__device__ int g_dst[MAXE];
__device__ int g_csr_src[MAXE];
__device__ int g_deg[MAXN];
__device__ int g_rowptr[MAXN + 1];
__device__ int g_wpos[MAXN];
__device__ int g_bsum[SCAN_NB];
__device__ int g_is64;

// ---------------- prep: dtype sniff + zero deg + convert W1 ----------------
__global__ void prep_kernel(const int* __restrict__ ei_raw,
                            const float* __restrict__ W1, int N) {
    int gt = blockIdx.x * blockDim.x + threadIdx.x;
    if (gt == 0) {
        int all0 = 1;
        for (int i = 0; i < 32; i++)
            if (ei_raw[2 * i + 1] != 0) { all0 = 0; break; }
        g_is64 = all0;
    }
    if (gt < N) g_deg[gt] = 0;
    if (gt < 128 * 128) {
        int k = gt >> 7, n = gt & 127;
        float a = W1[k * 128 + n];
        __nv_bfloat16 hv = __float2bfloat16(a);
        g_w1thi[n * 128 + k] = hv;
        g_w1tlo[n * 128 + k] = __float2bfloat16(a - __bfloat162float(hv));
    }
}

// ---------------- decode + degree count fused ----------------
__global__ void decode_count_kernel(const void* __restrict__ ei, int E, int N) {
    int e = blockIdx.x * blockDim.x + threadIdx.x;
    if (e >= E) return;
    int s, d;
    if (g_is64) {
        s = (int)((const long long*)ei)[e];
        d = (int)((const long long*)ei)[E + e];
    } else {
        s = ((const int*)ei)[e];
        d = ((const int*)ei)[E + e];
    }
    s = s < 0 ? 0 : (s >= N ? N - 1 : s);
    d = d < 0 ? 0 : (d >= N ? N - 1 : d);
    g_src[e] = s;
    g_dst[e] = d;
    atomicAdd(&g_deg[d], 1);
}

// ---------------- scan part 1: per-block exclusive scan + block sums ----------------
__global__ void scan1_kernel(int N) {
    __shared__ int s[256];
    int t = threadIdx.x;
    int i = blockIdx.x * 256 + t;
    int v = (i < N) ? g_deg[i] : 0;
    s[t] = v;
    for (int off = 1; off < 256; off <<= 1) {
        __syncthreads();
        int tv = (t >= off) ? s[t - off] : 0;
        __syncthreads();
        s[t] += tv;
    }
    __syncthreads();
    if (i < N) g_rowptr[i] = s[t] - v;
    if (t == 255) g_bsum[blockIdx.x] = s[255];
}

// ---------------- scan part 2: add prefix of block sums ----------------
__global__ void scan3_kernel(int N, int E, int nb) {
    __shared__ int red[256];
    int t = threadIdx.x;
    int blk = blockIdx.x;
    int part = 0;
    for (int i = t; i < blk; i += 256) part += g_bsum[i];
    red[t] = part;
    __syncthreads();
    for (int off = 128; off > 0; off >>= 1) {
        if (t < off) red[t] += red[t + off];
        __syncthreads();
    }
    int offv = red[0];
    int i = blk * 256 + t;
    if (i < N) {
        int r = g_rowptr[i] + offv;
        g_rowptr[i] = r;
        g_wpos[i] = r;
    }
    if (i == 0) g_rowptr[N] = E;
}

__global__ void scatter_kernel(int E) {
    int e = blockIdx.x * blockDim.x + threadIdx.x;
    if (e >= E) return;
    int d = g_dst[e];
    int p = atomicAdd(&g_wpos[d], 1);
    g_csr_src[p] = g_src[e];
}

// ---------------- mma / ldmatrix helpers ----------------
__device__ __forceinline__ void mma_bf16(float* c, uint32_t a0, uint32_t a1,
                                         uint32_t a2, uint32_t a3,
                                         uint32_t b0, uint32_t b1) {
    asm volatile(
        "mma.sync.aligned.m16n8k16.row.col.f32.bf16.bf16.f32 "
        "{%0,%1,%2,%3}, {%4,%5,%6,%7}, {%8,%9}, {%0,%1,%2,%3};\n"
        : "+f"(c[0]), "+f"(c[1]), "+f"(c[2]), "+f"(c[3])
        : "r"(a0), "r"(a1), "r"(a2), "r"(a3), "r"(b0), "r"(b1));
}

__device__ __forceinline__ void ldsm_x4(uint32_t* r, const void* p) {
    uint32_t addr = (uint32_t)__cvta_generic_to_shared(p);
    asm volatile("ldmatrix.sync.aligned.m8n8.x4.shared.b16 {%0,%1,%2,%3}, [%4];"
                 : "=r"(r[0]), "=r"(r[1]), "=r"(r[2]), "=r"(r[3]) : "r"(addr));
}

__device__ __forceinline__ uint32_t pack_hi2(float a, float b) {
    __nv_bfloat162 p = __floats2bfloat162_rn(a, b);
    return *(uint32_t*)&p;
}

// ---------------- GEMM1 (tensor): h1h[N,128] = x[N,128] @ W1 via bf16x3; ldmatrix path ----------------
// Shared rows padded to 12 words (48B): LDSM phases (8 rows x 16B, 12r mod 32) hit all banks once.
__global__ __launch_bounds__(256) void gemm1_tc_kernel(const float* __restrict__ x, int N) {
    __shared__ uint32_t As[2][128][12];  // [part][row][kpair padded]
    __shared__ uint32_t Bs[2][128][12];  // [part][n][kpair padded]
    int tid = threadIdx.x;
    int lane = tid & 31, wid = tid >> 5;
    int gid = lane >> 2, tig = lane & 3;
    int wm = (wid >> 1) * 32, wn = (wid & 1) * 64;
    int rowbase = blockIdx.x * 128;
    int q = lane >> 3, qr = lane & 7;       // ldmatrix quad + row-in-tile
    float c[2][8][4];
#pragma unroll
    for (int mt = 0; mt < 2; mt++)
#pragma unroll
        for (int nt = 0; nt < 8; nt++)
#pragma unroll
            for (int r = 0; r < 4; r++) c[mt][nt][r] = 0.f;

    for (int k0 = 0; k0 < 128; k0 += 16) {
        {   // A tile: load fp32 x, split to hi/lo in regs, store both parts
            int row = tid >> 1, hf = (tid & 1) * 4;  // 8 floats per thread
            int grow = rowbase + row;
            float4 v0 = make_float4(0.f, 0.f, 0.f, 0.f), v1 = v0;
            if (grow < N) {
                const float* p = &x[grow * 128 + k0 + hf * 2];
                v0 = *(const float4*)p;
                v1 = *(const float4*)(p + 4);
            }
            float f[8] = {v0.x, v0.y, v0.z, v0.w, v1.x, v1.y, v1.z, v1.w};
            uint32_t hi[4], lo[4];
#pragma unroll
            for (int qq = 0; qq < 4; qq++) {
                float a = f[2 * qq], b = f[2 * qq + 1];
                float ha = __bfloat162float(__float2bfloat16(a));
                float hb = __bfloat162float(__float2bfloat16(b));
                hi[qq] = pack_hi2(a, b);
                lo[qq] = pack_hi2(a - ha, b - hb);
            }
            *(uint4*)&As[0][row][hf] = make_uint4(hi[0], hi[1], hi[2], hi[3]);
            *(uint4*)&As[1][row][hf] = make_uint4(lo[0], lo[1], lo[2], lo[3]);
        }
#pragma unroll
        for (int i = 0; i < 2; i++) {  // B tile
            int cc = tid + i * 256;
            int part = cc >> 8, rem = cc & 255;
            int n = rem >> 1, hf = (rem & 1) * 4;
            const __nv_bfloat16* sp = part ? g_w1tlo : g_w1thi;
            *(uint4*)&Bs[part][n][hf] = *(const uint4*)&sp[n * 128 + k0 + hf * 2];
        }
        __syncthreads();
        // A fragments: tiles (r,k0-7),(r+8,k0-7),(r,k8-15),(r+8,k8-15) -> a0..a3
        uint32_t af[2][2][4];
#pragma unroll
        for (int p = 0; p < 2; p++)
#pragma unroll
            for (int mt = 0; mt < 2; mt++) {
                int trow = wm + mt * 16 + (q & 1) * 8 + qr;
                int chunk = (q >> 1) * 4;
                ldsm_x4(af[p][mt], &As[p][trow][chunk]);
            }
#pragma unroll
        for (int combo = 0; combo < 3; combo++) {
            int pa = (combo == 2) ? 1 : 0;
            int pb = (combo == 1) ? 1 : 0;
            // B fragments: tiles (n,k0-7),(n,k8-15),(n+8,k0-7),(n+8,k8-15)
            uint32_t bf[8][2];
#pragma unroll
            for (int ntp = 0; ntp < 4; ntp++) {
                int nrow = wn + ntp * 16 + (q >> 1) * 8 + qr;
                int chunk = (q & 1) * 4;
                uint32_t tmp[4];
                ldsm_x4(tmp, &Bs[pb][nrow][chunk]);
                bf[2 * ntp][0] = tmp[0]; bf[2 * ntp][1] = tmp[1];
                bf[2 * ntp + 1][0] = tmp[2]; bf[2 * ntp + 1][1] = tmp[3];
            }
#pragma unroll
            for (int nt = 0; nt < 8; nt++) {
                mma_bf16(c[0][nt], af[pa][0][0], af[pa][0][1], af[pa][0][2], af[pa][0][3],
                         bf[nt][0], bf[nt][1]);
                mma_bf16(c[1][nt], af[pa][1][0], af[pa][1][1], af[pa][1][2], af[pa][1][3],
                         bf[nt][0], bf[nt][1]);
            }
        }
        __syncthreads();
    }
#pragma unroll
    for (int mt = 0; mt < 2; mt++)
#pragma unroll
        for (int nt = 0; nt < 8; nt++) {
            int row = rowbase + wm + mt * 16 + gid;
            int col = wn + nt * 8 + tig * 2;
            if (row < N)
                *(__half2*)&g_h1h[row * 128 + col] = __floats2half2_rn(c[mt][nt][0], c[mt][nt][1]);
            if (row + 8 < N)
                *(__half2*)&g_h1h[(row + 8) * 128 + col] = __floats2half2_rn(c[mt][nt][2], c[mt][nt][3]);
        }
}

// ---------------- attention halves for layer 1 ----------------
__global__ __launch_bounds__(256) void attn1_kernel(const float* __restrict__ a_src,
                                                    const float* __restrict__ a_dst, int N) {
    int i = blockIdx.x * blockDim.x + threadIdx.x;
    if (i >= N * H) return;
    int hh = i & 3;
    const __half* row = g_h1h + (size_t)i * 32;
    const float* av = a_src + hh * 32;
    const float* bv = a_dst + hh * 32;
    float s = 0.f, d = 0.f;
#pragma unroll
    for (int f = 0; f < 32; f += 2) {
        float2 hv = __half22float2(*(const __half2*)&row[f]);
        s += hv.x * av[f] + hv.y * av[f + 1];
        d += hv.x * bv[f] + hv.y * bv[f + 1];
    }
    g_as1[i] = s;
    g_ad1[i] = d;
}

// ---------------- gather layer 1 FUSED (Round-12 form): softmax-agg + mean + bias + relu + gemm2 + attn2 ----------------
__global__ __launch_bounds__(256) void gather1_fused_kernel(const float* __restrict__ b,
                                                            const float* __restrict__ W2,
                                                            const float* __restrict__ a2s,
                                                            const float* __restrict__ a2d,
                                                            int N) {
    __shared__ float2 Ws[32][32];     // W2 as float2: Ws[k][c] = (W2[k][2c], W2[k][2c+1])
    __shared__ float x2buf[8][32];    // per-warp x2 row
    int tid = threadIdx.x;
#pragma unroll
    for (int i = 0; i < 4; i++) {
        int idx = tid + i * 256;          // 0..1023
        int k = idx >> 5, c = idx & 31;
        Ws[k][c] = *(const float2*)&W2[k * 64 + c * 2];
    }
    __syncthreads();

    int gt = blockIdx.x * 256 + tid;
    int d = gt >> 5;
    if (d >= N) return;
    int lane = gt & 31;
    int w = (tid >> 5);
    int head = lane >> 3;
    int beg = g_rowptr[d], end = g_rowptr[d + 1];
    float adh = g_ad1[d * 4 + head];
    float a0 = 0.f, a1 = 0.f, a2 = 0.f, a3 = 0.f, dsum = 0.f;
    int j = beg;
    for (; j + 2 <= end; j += 2) {
        int s0 = g_csr_src[j];
        int s1 = g_csr_src[j + 1];
        float sc0 = g_as1[s0 * 4 + head] + adh;
        float sc1 = g_as1[s1 * 4 + head] + adh;
        uint2 r0 = *(const uint2*)&g_h1h[s0 * 128 + lane * 4];
        uint2 r1 = *(const uint2*)&g_h1h[s1 * 128 + lane * 4];
        sc0 = sc0 > 0.f ? sc0 : NEG * sc0;
        sc1 = sc1 > 0.f ? sc1 : NEG * sc1;
        float e0 = __expf(sc0), e1 = __expf(sc1);
        float2 f00 = __half22float2(*(__half2*)&r0.x);
        float2 f01 = __half22float2(*(__half2*)&r0.y);
        float2 f10 = __half22float2(*(__half2*)&r1.x);
        float2 f11 = __half22float2(*(__half2*)&r1.y);
        a0 += e0 * f00.x + e1 * f10.x;
        a1 += e0 * f00.y + e1 * f10.y;
        a2 += e0 * f01.x + e1 * f11.x;
        a3 += e0 * f01.y + e1 * f11.y;
        dsum += e0 + e1;
    }
    if (j < end) {
        int s = g_csr_src[j];
        float sc = g_as1[s * 4 + head] + adh;
        sc = sc > 0.f ? sc : NEG * sc;
        float ex = __expf(sc);
        uint2 raw = *(const uint2*)&g_h1h[s * 128 + lane * 4];
        float2 f0 = __half22float2(*(__half2*)&raw.x);
        float2 f1 = __half22float2(*(__half2*)&raw.y);
        a0 += ex * f0.x; a1 += ex * f0.y; a2 += ex * f1.x; a3 += ex * f1.y;
        dsum += ex;
    }
    float inv = 1.f / (dsum + EPSF);
    a0 *= inv; a1 *= inv; a2 *= inv; a3 *= inv;
#pragma unroll
    for (int m = 8; m <= 16; m <<= 1) {
        a0 += __shfl_xor_sync(0xffffffffu, a0, m);
        a1 += __shfl_xor_sync(0xffffffffu, a1, m);
        a2 += __shfl_xor_sync(0xffffffffu, a2, m);
        a3 += __shfl_xor_sync(0xffffffffu, a3, m);
    }
    if (lane < 8) {
        float4 bb = *(const float4*)&b[lane * 4];
        float o0 = 0.25f * a0 + bb.x, o1 = 0.25f * a1 + bb.y;
        float o2 = 0.25f * a2 + bb.z, o3 = 0.25f * a3 + bb.w;
        x2buf[w][lane * 4 + 0] = o0 > 0.f ? o0 : 0.f;
        x2buf[w][lane * 4 + 1] = o1 > 0.f ? o1 : 0.f;
        x2buf[w][lane * 4 + 2] = o2 > 0.f ? o2 : 0.f;
        x2buf[w][lane * 4 + 3] = o3 > 0.f ? o3 : 0.f;
    }
    __syncwarp();
    // gemm2 row: h2[c0], h2[c1] for c0 = lane*2, c1 = lane*2+1
    float h0 = 0.f, h1 = 0.f;
#pragma unroll
    for (int k = 0; k < 32; k++) {
        float xv = x2buf[w][k];      // broadcast
        float2 wv = Ws[k][lane];
        h0 += xv * wv.x;
        h1 += xv * wv.y;
    }
    *(__half2*)&g_h2h[d * 64 + lane * 2] = __floats2half2_rn(h0, h1);
    // attn2
    int c0f = (lane * 2) & 15;
    int h2d = lane >> 3;
    float ps = h0 * a2s[h2d * 16 + c0f] + h1 * a2s[h2d * 16 + c0f + 1];
    float pd = h0 * a2d[h2d * 16 + c0f] + h1 * a2d[h2d * 16 + c0f + 1];
#pragma unroll
    for (int m = 1; m <= 4; m <<= 1) {
        ps += __shfl_xor_sync(0xffffffffu, ps, m);
        pd += __shfl_xor_sync(0xffffffffu, pd, m);
    }
    if ((lane & 7) == 0) {
        g_as2[d * 4 + h2d] = ps;
        g_ad2[d * 4 + h2d] = pd;
    }
}

// ---------------- gather layer 2 (Round-12 form): warp/dst, 2 edge subgroups ----------------
__global__ __launch_bounds__(256) void gather2_kernel(const float* __restrict__ b,
                                                      float* __restrict__ out, int N) {
    int gt = blockIdx.x * 256 + threadIdx.x;
    int d = gt >> 5;
    if (d >= N) return;
    int lane = gt & 31;
    int sub = lane >> 4;      // edge parity
    int l = lane & 15;        // feats l*4..l*4+3
    int head = l >> 2;
    int beg = g_rowptr[d], end = g_rowptr[d + 1];
    float adh = g_ad2[d * 4 + head];
    float a0 = 0.f, a1 = 0.f, a2 = 0.f, a3 = 0.f, dsum = 0.f;
    for (int j = beg + sub; j < end; j += 2) {
        int s = g_csr_src[j];
        float sc = g_as2[s * 4 + head] + adh;
        sc = sc > 0.f ? sc : NEG * sc;
        float ex = __expf(sc);
        uint2 raw = *(const uint2*)&g_h2h[s * 64 + l * 4];
        float2 f0 = __half22float2(*(__half2*)&raw.x);
        float2 f1 = __half22float2(*(__half2*)&raw.y);
        a0 += ex * f0.x; a1 += ex * f0.y; a2 += ex * f1.x; a3 += ex * f1.y;
        dsum += ex;
    }
    // combine edge halves
    a0 += __shfl_xor_sync(0xffffffffu, a0, 16);
    a1 += __shfl_xor_sync(0xffffffffu, a1, 16);
    a2 += __shfl_xor_sync(0xffffffffu, a2, 16);
    a3 += __shfl_xor_sync(0xffffffffu, a3, 16);
    dsum += __shfl_xor_sync(0xffffffffu, dsum, 16);
    float inv = 1.f / (dsum + EPSF);
    a0 *= inv; a1 *= inv; a2 *= inv; a3 *= inv;
    // mean over heads (head bits 2,3 of l)
#pragma unroll
    for (int m = 4; m <= 8; m <<= 1) {
        a0 += __shfl_xor_sync(0xffffffffu, a0, m);
        a1 += __shfl_xor_sync(0xffffffffu, a1, m);
        a2 += __shfl_xor_sync(0xffffffffu, a2, m);
        a3 += __shfl_xor_sync(0xffffffffu, a3, m);
    }
    if (lane < 4) {
        float4 bb = *(const float4*)&b[lane * 4];
        float4 o;
        o.x = 0.25f * a0 + bb.x; o.y = 0.25f * a1 + bb.y;
        o.z = 0.25f * a2 + bb.z; o.w = 0.25f * a3 + bb.w;
        *(float4*)&out[d * 16 + lane * 4] = o;
    }
}

extern "C" void kernel_launch(void* const* d_in, const int* in_sizes, int n_in,
                              void* d_out, int out_size) {
    const float* x = (const float*)d_in[0];
    const void* ei = d_in[1];
    const float* W1 = (const float*)d_in[2];
    const float* a1s = (const float*)d_in[3];
    const float* a1d = (const float*)d_in[4];
    const float* b1 = (const float*)d_in[5];
    const float* W2 = (const float*)d_in[6];
    const float* a2s = (const float*)d_in[7];
    const float* a2d = (const float*)d_in[8];
    const float* b2 = (const float*)d_in[9];
    int N = in_sizes[0] / 128;
    int E = in_sizes[1] / 2;
    if (N > MAXN) N = MAXN;
    if (E > MAXE) E = MAXE;
    float* out = (float*)d_out;
    int nb = (N + 255) / 256;
    int grid_e = (E + 255) / 256;
    int grid_warp = (N * 32 + 255) / 256;
    int grid_g = (N + 127) / 128;

    prep_kernel<<<nb, 256>>>((const int*)ei, W1, N);                 // 1
    decode_count_kernel<<<grid_e, 256>>>(ei, E, N);                  // 2
    scan1_kernel<<<nb, 256>>>(N);                                    // 3
    gemm1_tc_kernel<<<grid_g, 256>>>(x, N);                          // 4  <- ncu samples launch #4
    scan3_kernel<<<nb, 256>>>(N, E, nb);                             // 5
    scatter_kernel<<<grid_e, 256>>>(E);                              // 6
    attn1_kernel<<<(N * 4 + 255) / 256, 256>>>(a1s, a1d, N);         // 7
    gather1_fused_kernel<<<grid_warp, 256>>>(b1, W2, a2s, a2d, N);   // 8
    gather2_kernel<<<grid_warp, 256>>>(b2, out, N);                  // 9
}

// round 16
// speedup vs baseline: 1.5094x; 1.0804x over previous
#include <cuda_runtime.h>
#include <cuda_fp16.h>
#include <cuda_bf16.h>
#include <cstdint>

#define H 4
#define MAXN 100000
#define MAXE 1000000
#define NEG 0.2f
#define EPSF 1e-16f
#define SCAN_NB ((MAXN + 255) / 256)

// ---------------- scratch (device globals; no allocation allowed) ----------------
__device__ __align__(16) __half g_h1h[MAXN * 128];          // layer1 features fp16
__device__ __align__(16) __half g_h2h[MAXN * 64];           // layer2 features fp16
__device__ __align__(16) __nv_bfloat16 g_w1thi[128 * 128];  // W1^T split [n][k]
__device__ __align__(16) __nv_bfloat16 g_w1tlo[128 * 128];
__device__ __align__(16) float g_as1[MAXN * H];
__device__ __align__(16) float g_ad1[MAXN * H];
__device__ __align__(16) float g_as2[MAXN * H];
__device__ __align__(16) float g_ad2[MAXN * H];
__device__ int g_src[MAXE];
__device__ int g_dst[MAXE];
__device__ int g_csr_src[MAXE];
__device__ int g_deg[MAXN];
__device__ int g_rowptr[MAXN + 1];
__device__ int g_wpos[MAXN];
__device__ int g_bsum[SCAN_NB];
__device__ int g_is64;

// ---------------- prep: dtype sniff + zero deg + convert W1 ----------------
__global__ void prep_kernel(const int* __restrict__ ei_raw,
                            const float* __restrict__ W1, int N) {
    int gt = blockIdx.x * blockDim.x + threadIdx.x;
    if (gt == 0) {
        int all0 = 1;
        for (int i = 0; i < 32; i++)
            if (ei_raw[2 * i + 1] != 0) { all0 = 0; break; }
        g_is64 = all0;
    }
    if (gt < N) g_deg[gt] = 0;
    if (gt < 128 * 128) {
        int k = gt >> 7, n = gt & 127;
        float a = W1[k * 128 + n];
        __nv_bfloat16 hv = __float2bfloat16(a);
        g_w1thi[n * 128 + k] = hv;
        g_w1tlo[n * 128 + k] = __float2bfloat16(a - __bfloat162float(hv));
    }
}

// ---------------- decode + degree count fused ----------------
__global__ void decode_count_kernel(const void* __restrict__ ei, int E, int N) {
    int e = blockIdx.x * blockDim.x + threadIdx.x;
    if (e >= E) return;
    int s, d;
    if (g_is64) {
        s = (int)((const long long*)ei)[e];
        d = (int)((const long long*)ei)[E + e];
    } else {
        s = ((const int*)ei)[e];
        d = ((const int*)ei)[E + e];
    }
    s = s < 0 ? 0 : (s >= N ? N - 1 : s);
    d = d < 0 ? 0 : (d >= N ? N - 1 : d);
    g_src[e] = s;
    g_dst[e] = d;
    atomicAdd(&g_deg[d], 1);
}

// ---------------- scan part 1: per-block exclusive scan + block sums ----------------
__global__ void scan1_kernel(int N) {
    __shared__ int s[256];
    int t = threadIdx.x;
    int i = blockIdx.x * 256 + t;
    int v = (i < N) ? g_deg[i] : 0;
    s[t] = v;
    for (int off = 1; off < 256; off <<= 1) {
        __syncthreads();
        int tv = (t >= off) ? s[t - off] : 0;
        __syncthreads();
        s[t] += tv;
    }
    __syncthreads();
    if (i < N) g_rowptr[i] = s[t] - v;
    if (t == 255) g_bsum[blockIdx.x] = s[255];
}

// ---------------- scan part 2: add prefix of block sums ----------------
__global__ void scan3_kernel(int N, int E, int nb) {
    __shared__ int red[256];
    int t = threadIdx.x;
    int blk = blockIdx.x;
    int part = 0;
    for (int i = t; i < blk; i += 256) part += g_bsum[i];
    red[t] = part;
    __syncthreads();
    for (int off = 128; off > 0; off >>= 1) {
        if (t < off) red[t] += red[t + off];
        __syncthreads();
    }
    int offv = red[0];
    int i = blk * 256 + t;
    if (i < N) {
        int r = g_rowptr[i] + offv;
        g_rowptr[i] = r;
        g_wpos[i] = r;
    }
    if (i == 0) g_rowptr[N] = E;
}

__global__ void scatter_kernel(int E) {
    int e = blockIdx.x * blockDim.x + threadIdx.x;
    if (e >= E) return;
    int d = g_dst[e];
    int p = atomicAdd(&g_wpos[d], 1);
    g_csr_src[p] = g_src[e];
}

// ---------------- mma / ldmatrix helpers ----------------
__device__ __forceinline__ void mma_bf16(float* c, uint32_t a0, uint32_t a1,
                                         uint32_t a2, uint32_t a3,
                                         uint32_t b0, uint32_t b1) {
    asm volatile(
        "mma.sync.aligned.m16n8k16.row.col.f32.bf16.bf16.f32 "
        "{%0,%1,%2,%3}, {%4,%5,%6,%7}, {%8,%9}, {%0,%1,%2,%3};\n"
        : "+f"(c[0]), "+f"(c[1]), "+f"(c[2]), "+f"(c[3])
        : "r"(a0), "r"(a1), "r"(a2), "r"(a3), "r"(b0), "r"(b1));
}

__device__ __forceinline__ void ldsm_x4(uint32_t* r, const void* p) {
    uint32_t addr = (uint32_t)__cvta_generic_to_shared(p);
    asm volatile("ldmatrix.sync.aligned.m8n8.x4.shared.b16 {%0,%1,%2,%3}, [%4];"
                 : "=r"(r[0]), "=r"(r[1]), "=r"(r[2]), "=r"(r[3]) : "r"(addr));
}

__device__ __forceinline__ uint32_t pack_hi2(float a, float b) {
    __nv_bfloat162 p = __floats2bfloat162_rn(a, b);
    return *(uint32_t*)&p;
}

// ---------------- GEMM1 (tensor): h1h[N,128] = x[N,128] @ W1 via bf16x3 ----------------
// M=64 tile per block (low regs, 2+ CTAs/SM). ldmatrix path, 12-word padded rows.
__global__ __launch_bounds__(256, 2) void gemm1_tc_kernel(const float* __restrict__ x, int N) {
    __shared__ uint32_t As[2][64][12];   // [part][row][kpair padded]
    __shared__ uint32_t Bs[2][128][12];  // [part][n][kpair padded]
    int tid = threadIdx.x;
    int lane = tid & 31, wid = tid >> 5;
    int gid = lane >> 2, tig = lane & 3;
    int wm = (wid >> 1) * 16, wn = (wid & 1) * 64;   // warp: 16 rows x 64 cols
    int rowbase = blockIdx.x * 64;
    int q = lane >> 3, qr = lane & 7;
    float c[8][4];
#pragma unroll
    for (int nt = 0; nt < 8; nt++)
#pragma unroll
        for (int r = 0; r < 4; r++) c[nt][r] = 0.f;

    for (int k0 = 0; k0 < 128; k0 += 16) {
        {   // A tile: 64 rows x 16 cols fp32; 256 threads x 4 floats; split hi/lo
            int row = tid >> 2, quar = tid & 3;
            int grow = rowbase + row;
            float4 v = make_float4(0.f, 0.f, 0.f, 0.f);
            if (grow < N) v = *(const float4*)&x[grow * 128 + k0 + quar * 4];
            float ha = __bfloat162float(__float2bfloat16(v.x));
            float hb = __bfloat162float(__float2bfloat16(v.y));
            float hc = __bfloat162float(__float2bfloat16(v.z));
            float hd = __bfloat162float(__float2bfloat16(v.w));
            uint2 hi = make_uint2(pack_hi2(v.x, v.y), pack_hi2(v.z, v.w));
            uint2 lo = make_uint2(pack_hi2(v.x - ha, v.y - hb), pack_hi2(v.z - hc, v.w - hd));
            *(uint2*)&As[0][row][quar * 2] = hi;
            *(uint2*)&As[1][row][quar * 2] = lo;
        }
#pragma unroll
        for (int i = 0; i < 2; i++) {  // B tile: 2 parts x 128 n x 8 u32 = 512 uint4
            int cc = tid + i * 256;
            int part = cc >> 8, rem = cc & 255;
            int n = rem >> 1, hf = (rem & 1) * 4;
            const __nv_bfloat16* sp = part ? g_w1tlo : g_w1thi;
            *(uint4*)&Bs[part][n][hf] = *(const uint4*)&sp[n * 128 + k0 + hf * 2];
        }
        __syncthreads();
        // A fragments for both parts (1 m-tile per warp)
        uint32_t af[2][4];
#pragma unroll
        for (int p = 0; p < 2; p++) {
            int trow = wm + (q & 1) * 8 + qr;
            int chunk = (q >> 1) * 4;
            ldsm_x4(af[p], &As[p][trow][chunk]);
        }
#pragma unroll
        for (int combo = 0; combo < 3; combo++) {
            int pa = (combo == 2) ? 1 : 0;
            int pb = (combo == 1) ? 1 : 0;
            uint32_t bf[8][2];
#pragma unroll
            for (int ntp = 0; ntp < 4; ntp++) {
                int nrow = wn + ntp * 16 + (q >> 1) * 8 + qr;
                int chunk = (q & 1) * 4;
                uint32_t tmp[4];
                ldsm_x4(tmp, &Bs[pb][nrow][chunk]);
                bf[2 * ntp][0] = tmp[0]; bf[2 * ntp][1] = tmp[1];
                bf[2 * ntp + 1][0] = tmp[2]; bf[2 * ntp + 1][1] = tmp[3];
            }
#pragma unroll
            for (int nt = 0; nt < 8; nt++)
                mma_bf16(c[nt], af[pa][0], af[pa][1], af[pa][2], af[pa][3],
                         bf[nt][0], bf[nt][1]);
        }
        __syncthreads();
    }
#pragma unroll
    for (int nt = 0; nt < 8; nt++) {
        int row = rowbase + wm + gid;
        int col = wn + nt * 8 + tig * 2;
        if (row < N)
            *(__half2*)&g_h1h[row * 128 + col] = __floats2half2_rn(c[nt][0], c[nt][1]);
        if (row + 8 < N)
            *(__half2*)&g_h1h[(row + 8) * 128 + col] = __floats2half2_rn(c[nt][2], c[nt][3]);
    }
}

// ---------------- attention halves for layer 1 ----------------
__global__ __launch_bounds__(256) void attn1_kernel(const float* __restrict__ a_src,
                                                    const float* __restrict__ a_dst, int N) {
    int i = blockIdx.x * blockDim.x + threadIdx.x;
    if (i >= N * H) return;
    int hh = i & 3;
    const __half* row = g_h1h + (size_t)i * 32;
    const float* av = a_src + hh * 32;
    const float* bv = a_dst + hh * 32;
    float s = 0.f, d = 0.f;
#pragma unroll
    for (int f = 0; f < 32; f += 2) {
        float2 hv = __half22float2(*(const __half2*)&row[f]);
        s += hv.x * av[f] + hv.y * av[f + 1];
        d += hv.x * bv[f] + hv.y * bv[f + 1];
    }
    g_as1[i] = s;
    g_ad1[i] = d;
}

// ---------------- gather layer 1 FUSED (Round-12 form): softmax-agg + mean + bias + relu + gemm2 + attn2 ----------------
__global__ __launch_bounds__(256) void gather1_fused_kernel(const float* __restrict__ b,
                                                            const float* __restrict__ W2,
                                                            const float* __restrict__ a2s,
                                                            const float* __restrict__ a2d,
                                                            int N) {
    __shared__ float2 Ws[32][32];     // W2 as float2: Ws[k][c] = (W2[k][2c], W2[k][2c+1])
    __shared__ float x2buf[8][32];    // per-warp x2 row
    int tid = threadIdx.x;
#pragma unroll
    for (int i = 0; i < 4; i++) {
        int idx = tid + i * 256;          // 0..1023
        int k = idx >> 5, c = idx & 31;
        Ws[k][c] = *(const float2*)&W2[k * 64 + c * 2];
    }
    __syncthreads();

    int gt = blockIdx.x * 256 + tid;
    int d = gt >> 5;
    if (d >= N) return;
    int lane = gt & 31;
    int w = (tid >> 5);
    int head = lane >> 3;
    int beg = g_rowptr[d], end = g_rowptr[d + 1];
    float adh = g_ad1[d * 4 + head];
    float a0 = 0.f, a1 = 0.f, a2 = 0.f, a3 = 0.f, dsum = 0.f;
    int j = beg;
    for (; j + 2 <= end; j += 2) {
        int s0 = g_csr_src[j];
        int s1 = g_csr_src[j + 1];
        float sc0 = g_as1[s0 * 4 + head] + adh;
        float sc1 = g_as1[s1 * 4 + head] + adh;
        uint2 r0 = *(const uint2*)&g_h1h[s0 * 128 + lane * 4];
        uint2 r1 = *(const uint2*)&g_h1h[s1 * 128 + lane * 4];
        sc0 = sc0 > 0.f ? sc0 : NEG * sc0;
        sc1 = sc1 > 0.f ? sc1 : NEG * sc1;
        float e0 = __expf(sc0), e1 = __expf(sc1);
        float2 f00 = __half22float2(*(__half2*)&r0.x);
        float2 f01 = __half22float2(*(__half2*)&r0.y);
        float2 f10 = __half22float2(*(__half2*)&r1.x);
        float2 f11 = __half22float2(*(__half2*)&r1.y);
        a0 += e0 * f00.x + e1 * f10.x;
        a1 += e0 * f00.y + e1 * f10.y;
        a2 += e0 * f01.x + e1 * f11.x;
        a3 += e0 * f01.y + e1 * f11.y;
        dsum += e0 + e1;
    }
    if (j < end) {
        int s = g_csr_src[j];
        float sc = g_as1[s * 4 + head] + adh;
        sc = sc > 0.f ? sc : NEG * sc;
        float ex = __expf(sc);
        uint2 raw = *(const uint2*)&g_h1h[s * 128 + lane * 4];
        float2 f0 = __half22float2(*(__half2*)&raw.x);
        float2 f1 = __half22float2(*(__half2*)&raw.y);
        a0 += ex * f0.x; a1 += ex * f0.y; a2 += ex * f1.x; a3 += ex * f1.y;
        dsum += ex;
    }
    float inv = 1.f / (dsum + EPSF);
    a0 *= inv; a1 *= inv; a2 *= inv; a3 *= inv;
#pragma unroll
    for (int m = 8; m <= 16; m <<= 1) {
        a0 += __shfl_xor_sync(0xffffffffu, a0, m);
        a1 += __shfl_xor_sync(0xffffffffu, a1, m);
        a2 += __shfl_xor_sync(0xffffffffu, a2, m);
        a3 += __shfl_xor_sync(0xffffffffu, a3, m);
    }
    if (lane < 8) {
        float4 bb = *(const float4*)&b[lane * 4];
        float o0 = 0.25f * a0 + bb.x, o1 = 0.25f * a1 + bb.y;
        float o2 = 0.25f * a2 + bb.z, o3 = 0.25f * a3 + bb.w;
        x2buf[w][lane * 4 + 0] = o0 > 0.f ? o0 : 0.f;
        x2buf[w][lane * 4 + 1] = o1 > 0.f ? o1 : 0.f;
        x2buf[w][lane * 4 + 2] = o2 > 0.f ? o2 : 0.f;
        x2buf[w][lane * 4 + 3] = o3 > 0.f ? o3 : 0.f;
    }
    __syncwarp();
    // gemm2 row: h2[c0], h2[c1] for c0 = lane*2, c1 = lane*2+1
    float h0 = 0.f, h1 = 0.f;
#pragma unroll
    for (int k = 0; k < 32; k++) {
        float xv = x2buf[w][k];      // broadcast
        float2 wv = Ws[k][lane];
        h0 += xv * wv.x;
        h1 += xv * wv.y;
    }
    *(__half2*)&g_h2h[d * 64 + lane * 2] = __floats2half2_rn(h0, h1);
    // attn2
    int c0f = (lane * 2) & 15;
    int h2d = lane >> 3;
    float ps = h0 * a2s[h2d * 16 + c0f] + h1 * a2s[h2d * 16 + c0f + 1];
    float pd = h0 * a2d[h2d * 16 + c0f] + h1 * a2d[h2d * 16 + c0f + 1];
#pragma unroll
    for (int m = 1; m <= 4; m <<= 1) {
        ps += __shfl_xor_sync(0xffffffffu, ps, m);
        pd += __shfl_xor_sync(0xffffffffu, pd, m);
    }
    if ((lane & 7) == 0) {
        g_as2[d * 4 + h2d] = ps;
        g_ad2[d * 4 + h2d] = pd;
    }
}

// ---------------- gather layer 2 (Round-12 form): warp/dst, 2 edge subgroups ----------------
__global__ __launch_bounds__(256) void gather2_kernel(const float* __restrict__ b,
                                                      float* __restrict__ out, int N) {
    int gt = blockIdx.x * 256 + threadIdx.x;
    int d = gt >> 5;
    if (d >= N) return;
    int lane = gt & 31;
    int sub = lane >> 4;      // edge parity
    int l = lane & 15;        // feats l*4..l*4+3
    int head = l >> 2;
    int beg = g_rowptr[d], end = g_rowptr[d + 1];
    float adh = g_ad2[d * 4 + head];
    float a0 = 0.f, a1 = 0.f, a2 = 0.f, a3 = 0.f, dsum = 0.f;
    for (int j = beg + sub; j < end; j += 2) {
        int s = g_csr_src[j];
        float sc = g_as2[s * 4 + head] + adh;
        sc = sc > 0.f ? sc : NEG * sc;
        float ex = __expf(sc);
        uint2 raw = *(const uint2*)&g_h2h[s * 64 + l * 4];
        float2 f0 = __half22float2(*(__half2*)&raw.x);
        float2 f1 = __half22float2(*(__half2*)&raw.y);
        a0 += ex * f0.x; a1 += ex * f0.y; a2 += ex * f1.x; a3 += ex * f1.y;
        dsum += ex;
    }
    // combine edge halves
    a0 += __shfl_xor_sync(0xffffffffu, a0, 16);
    a1 += __shfl_xor_sync(0xffffffffu, a1, 16);
    a2 += __shfl_xor_sync(0xffffffffu, a2, 16);
    a3 += __shfl_xor_sync(0xffffffffu, a3, 16);
    dsum += __shfl_xor_sync(0xffffffffu, dsum, 16);
    float inv = 1.f / (dsum + EPSF);
    a0 *= inv; a1 *= inv; a2 *= inv; a3 *= inv;
    // mean over heads (head bits 2,3 of l)
#pragma unroll
    for (int m = 4; m <= 8; m <<= 1) {
        a0 += __shfl_xor_sync(0xffffffffu, a0, m);
        a1 += __shfl_xor_sync(0xffffffffu, a1, m);
        a2 += __shfl_xor_sync(0xffffffffu, a2, m);
        a3 += __shfl_xor_sync(0xffffffffu, a3, m);
    }
    if (lane < 4) {
        float4 bb = *(const float4*)&b[lane * 4];
        float4 o;
        o.x = 0.25f * a0 + bb.x; o.y = 0.25f * a1 + bb.y;
        o.z = 0.25f * a2 + bb.z; o.w = 0.25f * a3 + bb.w;
        *(float4*)&out[d * 16 + lane * 4] = o;
    }
}

extern "C" void kernel_launch(void* const* d_in, const int* in_sizes, int n_in,
                              void* d_out, int out_size) {
    const float* x = (const float*)d_in[0];
    const void* ei = d_in[1];
    const float* W1 = (const float*)d_in[2];
    const float* a1s = (const float*)d_in[3];
    const float* a1d = (const float*)d_in[4];
    const float* b1 = (const float*)d_in[5];
    const float* W2 = (const float*)d_in[6];
    const float* a2s = (const float*)d_in[7];
    const float* a2d = (const float*)d_in[8];
    const float* b2 = (const float*)d_in[9];
    int N = in_sizes[0] / 128;
    int E = in_sizes[1] / 2;
    if (N > MAXN) N = MAXN;
    if (E > MAXE) E = MAXE;
    float* out = (float*)d_out;
    int nb = (N + 255) / 256;
    int grid_e = (E + 255) / 256;
    int grid_warp = (N * 32 + 255) / 256;
    int grid_g = (N + 63) / 64;

    prep_kernel<<<nb, 256>>>((const int*)ei, W1, N);                 // 1
    decode_count_kernel<<<grid_e, 256>>>(ei, E, N);                  // 2
    scan1_kernel<<<nb, 256>>>(N);                                    // 3
    gemm1_tc_kernel<<<grid_g, 256>>>(x, N);                          // 4  <- ncu samples launch #4
    scan3_kernel<<<nb, 256>>>(N, E, nb);                             // 5
    scatter_kernel<<<grid_e, 256>>>(E);                              // 6
    attn1_kernel<<<(N * 4 + 255) / 256, 256>>>(a1s, a1d, N);         // 7
    gather1_fused_kernel<<<grid_warp, 256>>>(b1, W2, a2s, a2d, N);   // 8
    gather2_kernel<<<grid_warp, 256>>>(b2, out, N);                  // 9
}

// round 17
// speedup vs baseline: 1.5672x; 1.0383x over previous
#include <cuda_runtime.h>
#include <cuda_fp16.h>
#include <cuda_bf16.h>
#include <cstdint>

#define H 4
#define MAXN 100000
#define MAXE 1000000
#define NEG 0.2f
#define EPSF 1e-16f
#define SCAN_NB ((MAXN + 255) / 256)

// ---------------- scratch (device globals; no allocation allowed) ----------------
__device__ __align__(16) __half g_h1h[MAXN * 128];          // layer1 features fp16
__device__ __align__(16) __half g_h2h[MAXN * 64];           // layer2 features fp16
__device__ __align__(16) __nv_bfloat16 g_w1thi[128 * 128];  // W1^T split [n][k]
__device__ __align__(16) __nv_bfloat16 g_w1tlo[128 * 128];
__device__ __align__(16) float g_as1[MAXN * H];
__device__ __align__(16) float g_ad1[MAXN * H];
__device__ __align__(16) float g_as2[MAXN * H];
__device__ __align__(16) float g_ad2[MAXN * H];
__device__ int g_src[MAXE];
__device__ int g_dst[MAXE];
__device__ int g_csr_src[MAXE];
__device__ int g_deg[MAXN];
__device__ int g_rowptr[MAXN + 1];
__device__ int g_wpos[MAXN];
__device__ int g_bsum[SCAN_NB];
__device__ int g_is64;

// ---------------- prep: dtype sniff + zero deg + convert W1 ----------------
__global__ void prep_kernel(const int* __restrict__ ei_raw,
                            const float* __restrict__ W1, int N) {
    int gt = blockIdx.x * blockDim.x + threadIdx.x;
    if (gt == 0) {
        int all0 = 1;
        for (int i = 0; i < 32; i++)
            if (ei_raw[2 * i + 1] != 0) { all0 = 0; break; }
        g_is64 = all0;
    }
    if (gt < N) g_deg[gt] = 0;
    if (gt < 128 * 128) {
        int k = gt >> 7, n = gt & 127;
        float a = W1[k * 128 + n];
        __nv_bfloat16 hv = __float2bfloat16(a);
        g_w1thi[n * 128 + k] = hv;
        g_w1tlo[n * 128 + k] = __float2bfloat16(a - __bfloat162float(hv));
    }
}

// ---------------- decode + degree count fused ----------------
__global__ void decode_count_kernel(const void* __restrict__ ei, int E, int N) {
    int e = blockIdx.x * blockDim.x + threadIdx.x;
    if (e >= E) return;
    int s, d;
    if (g_is64) {
        s = (int)((const long long*)ei)[e];
        d = (int)((const long long*)ei)[E + e];
    } else {
        s = ((const int*)ei)[e];
        d = ((const int*)ei)[E + e];
    }
    s = s < 0 ? 0 : (s >= N ? N - 1 : s);
    d = d < 0 ? 0 : (d >= N ? N - 1 : d);
    g_src[e] = s;
    g_dst[e] = d;
    atomicAdd(&g_deg[d], 1);
}

// ---------------- scan part 1: per-block exclusive scan + block sums ----------------
__global__ void scan1_kernel(int N) {
    __shared__ int s[256];
    int t = threadIdx.x;
    int i = blockIdx.x * 256 + t;
    int v = (i < N) ? g_deg[i] : 0;
    s[t] = v;
    for (int off = 1; off < 256; off <<= 1) {
        __syncthreads();
        int tv = (t >= off) ? s[t - off] : 0;
        __syncthreads();
        s[t] += tv;
    }
    __syncthreads();
    if (i < N) g_rowptr[i] = s[t] - v;
    if (t == 255) g_bsum[blockIdx.x] = s[255];
}

// ---------------- scan part 2: add prefix of block sums ----------------
__global__ void scan3_kernel(int N, int E, int nb) {
    __shared__ int red[256];
    int t = threadIdx.x;
    int blk = blockIdx.x;
    int part = 0;
    for (int i = t; i < blk; i += 256) part += g_bsum[i];
    red[t] = part;
    __syncthreads();
    for (int off = 128; off > 0; off >>= 1) {
        if (t < off) red[t] += red[t + off];
        __syncthreads();
    }
    int offv = red[0];
    int i = blk * 256 + t;
    if (i < N) {
        int r = g_rowptr[i] + offv;
        g_rowptr[i] = r;
        g_wpos[i] = r;
    }
    if (i == 0) g_rowptr[N] = E;
}

__global__ void scatter_kernel(int E) {
    int e = blockIdx.x * blockDim.x + threadIdx.x;
    if (e >= E) return;
    int d = g_dst[e];
    int p = atomicAdd(&g_wpos[d], 1);
    g_csr_src[p] = g_src[e];
}

// ---------------- mma / ldmatrix helpers ----------------
__device__ __forceinline__ void mma_bf16(float* c, uint32_t a0, uint32_t a1,
                                         uint32_t a2, uint32_t a3,
                                         uint32_t b0, uint32_t b1) {
    asm volatile(
        "mma.sync.aligned.m16n8k16.row.col.f32.bf16.bf16.f32 "
        "{%0,%1,%2,%3}, {%4,%5,%6,%7}, {%8,%9}, {%0,%1,%2,%3};\n"
        : "+f"(c[0]), "+f"(c[1]), "+f"(c[2]), "+f"(c[3])
        : "r"(a0), "r"(a1), "r"(a2), "r"(a3), "r"(b0), "r"(b1));
}

__device__ __forceinline__ void ldsm_x4(uint32_t* r, const void* p) {
    uint32_t addr = (uint32_t)__cvta_generic_to_shared(p);
    asm volatile("ldmatrix.sync.aligned.m8n8.x4.shared.b16 {%0,%1,%2,%3}, [%4];"
                 : "=r"(r[0]), "=r"(r[1]), "=r"(r[2]), "=r"(r[3]) : "r"(addr));
}

__device__ __forceinline__ uint32_t pack_hi2(float a, float b) {
    __nv_bfloat162 p = __floats2bfloat162_rn(a, b);
    return *(uint32_t*)&p;
}

// ---------------- GEMM1 (tensor): h1h[N,128] = x[N,128] @ W1 via bf16x3 ----------------
// M=64 tile per block. ldmatrix path, 12-word padded rows.
// Combo loop ordered pb-outer so each B part's fragments are loaded ONCE per k-step.
__global__ __launch_bounds__(256, 2) void gemm1_tc_kernel(const float* __restrict__ x, int N) {
    __shared__ uint32_t As[2][64][12];   // [part][row][kpair padded]
    __shared__ uint32_t Bs[2][128][12];  // [part][n][kpair padded]
    int tid = threadIdx.x;
    int lane = tid & 31, wid = tid >> 5;
    int gid = lane >> 2, tig = lane & 3;
    int wm = (wid >> 1) * 16, wn = (wid & 1) * 64;   // warp: 16 rows x 64 cols
    int rowbase = blockIdx.x * 64;
    int q = lane >> 3, qr = lane & 7;
    float c[8][4];
#pragma unroll
    for (int nt = 0; nt < 8; nt++)
#pragma unroll
        for (int r = 0; r < 4; r++) c[nt][r] = 0.f;

    for (int k0 = 0; k0 < 128; k0 += 16) {
        {   // A tile: 64 rows x 16 cols fp32; 256 threads x 4 floats; split hi/lo
            int row = tid >> 2, quar = tid & 3;
            int grow = rowbase + row;
            float4 v = make_float4(0.f, 0.f, 0.f, 0.f);
            if (grow < N) v = *(const float4*)&x[grow * 128 + k0 + quar * 4];
            float ha = __bfloat162float(__float2bfloat16(v.x));
            float hb = __bfloat162float(__float2bfloat16(v.y));
            float hc = __bfloat162float(__float2bfloat16(v.z));
            float hd = __bfloat162float(__float2bfloat16(v.w));
            uint2 hi = make_uint2(pack_hi2(v.x, v.y), pack_hi2(v.z, v.w));
            uint2 lo = make_uint2(pack_hi2(v.x - ha, v.y - hb), pack_hi2(v.z - hc, v.w - hd));
            *(uint2*)&As[0][row][quar * 2] = hi;
            *(uint2*)&As[1][row][quar * 2] = lo;
        }
#pragma unroll
        for (int i = 0; i < 2; i++) {  // B tile: 2 parts x 128 n x 8 u32 = 512 uint4
            int cc = tid + i * 256;
            int part = cc >> 8, rem = cc & 255;
            int n = rem >> 1, hf = (rem & 1) * 4;
            const __nv_bfloat16* sp = part ? g_w1tlo : g_w1thi;
            *(uint4*)&Bs[part][n][hf] = *(const uint4*)&sp[n * 128 + k0 + hf * 2];
        }
        __syncthreads();
        // A fragments for both parts (1 m-tile per warp)
        uint32_t af[2][4];
#pragma unroll
        for (int p = 0; p < 2; p++) {
            int trow = wm + (q & 1) * 8 + qr;
            int chunk = (q >> 1) * 4;
            ldsm_x4(af[p], &As[p][trow][chunk]);
        }
        // combos {hi*hi, lo*hi, hi*lo} with pb outer: B fragments loaded once per part
#pragma unroll
        for (int pb = 0; pb < 2; pb++) {
            uint32_t bf[8][2];
#pragma unroll
            for (int ntp = 0; ntp < 4; ntp++) {
                int nrow = wn + ntp * 16 + (q >> 1) * 8 + qr;
                int chunk = (q & 1) * 4;
                uint32_t tmp[4];
                ldsm_x4(tmp, &Bs[pb][nrow][chunk]);
                bf[2 * ntp][0] = tmp[0]; bf[2 * ntp][1] = tmp[1];
                bf[2 * ntp + 1][0] = tmp[2]; bf[2 * ntp + 1][1] = tmp[3];
            }
            int npa = (pb == 0) ? 2 : 1;
#pragma unroll
            for (int pa = 0; pa < 2; pa++) {
                if (pa >= npa) break;
#pragma unroll
                for (int nt = 0; nt < 8; nt++)
                    mma_bf16(c[nt], af[pa][0], af[pa][1], af[pa][2], af[pa][3],
                             bf[nt][0], bf[nt][1]);
            }
        }
        __syncthreads();
    }
#pragma unroll
    for (int nt = 0; nt < 8; nt++) {
        int row = rowbase + wm + gid;
        int col = wn + nt * 8 + tig * 2;
        if (row < N)
            *(__half2*)&g_h1h[row * 128 + col] = __floats2half2_rn(c[nt][0], c[nt][1]);
        if (row + 8 < N)
            *(__half2*)&g_h1h[(row + 8) * 128 + col] = __floats2half2_rn(c[nt][2], c[nt][3]);
    }
}

// ---------------- attention halves for layer 1 ----------------
__global__ __launch_bounds__(256) void attn1_kernel(const float* __restrict__ a_src,
                                                    const float* __restrict__ a_dst, int N) {
    int i = blockIdx.x * blockDim.x + threadIdx.x;
    if (i >= N * H) return;
    int hh = i & 3;
    const __half* row = g_h1h + (size_t)i * 32;
    const float* av = a_src + hh * 32;
    const float* bv = a_dst + hh * 32;
    float s = 0.f, d = 0.f;
#pragma unroll
    for (int f = 0; f < 32; f += 2) {
        float2 hv = __half22float2(*(const __half2*)&row[f]);
        s += hv.x * av[f] + hv.y * av[f + 1];
        d += hv.x * bv[f] + hv.y * bv[f + 1];
    }
    g_as1[i] = s;
    g_ad1[i] = d;
}

// ---------------- gather layer 1 FUSED (Round-12 form): softmax-agg + mean + bias + relu + gemm2 + attn2 ----------------
__global__ __launch_bounds__(256) void gather1_fused_kernel(const float* __restrict__ b,
                                                            const float* __restrict__ W2,
                                                            const float* __restrict__ a2s,
                                                            const float* __restrict__ a2d,
                                                            int N) {
    __shared__ float2 Ws[32][32];     // W2 as float2: Ws[k][c] = (W2[k][2c], W2[k][2c+1])
    __shared__ float x2buf[8][32];    // per-warp x2 row
    int tid = threadIdx.x;
#pragma unroll
    for (int i = 0; i < 4; i++) {
        int idx = tid + i * 256;          // 0..1023
        int k = idx >> 5, c = idx & 31;
        Ws[k][c] = *(const float2*)&W2[k * 64 + c * 2];
    }
    __syncthreads();

    int gt = blockIdx.x * 256 + tid;
    int d = gt >> 5;
    if (d >= N) return;
    int lane = gt & 31;
    int w = (tid >> 5);
    int head = lane >> 3;
    int beg = g_rowptr[d], end = g_rowptr[d + 1];
    float adh = g_ad1[d * 4 + head];
    float a0 = 0.f, a1 = 0.f, a2 = 0.f, a3 = 0.f, dsum = 0.f;
    int j = beg;
    for (; j + 2 <= end; j += 2) {
        int s0 = g_csr_src[j];
        int s1 = g_csr_src[j + 1];
        float sc0 = g_as1[s0 * 4 + head] + adh;
        float sc1 = g_as1[s1 * 4 + head] + adh;
        uint2 r0 = *(const uint2*)&g_h1h[s0 * 128 + lane * 4];
        uint2 r1 = *(const uint2*)&g_h1h[s1 * 128 + lane * 4];
        sc0 = sc0 > 0.f ? sc0 : NEG * sc0;
        sc1 = sc1 > 0.f ? sc1 : NEG * sc1;
        float e0 = __expf(sc0), e1 = __expf(sc1);
        float2 f00 = __half22float2(*(__half2*)&r0.x);
        float2 f01 = __half22float2(*(__half2*)&r0.y);
        float2 f10 = __half22float2(*(__half2*)&r1.x);
        float2 f11 = __half22float2(*(__half2*)&r1.y);
        a0 += e0 * f00.x + e1 * f10.x;
        a1 += e0 * f00.y + e1 * f10.y;
        a2 += e0 * f01.x + e1 * f11.x;
        a3 += e0 * f01.y + e1 * f11.y;
        dsum += e0 + e1;
    }
    if (j < end) {
        int s = g_csr_src[j];
        float sc = g_as1[s * 4 + head] + adh;
        sc = sc > 0.f ? sc : NEG * sc;
        float ex = __expf(sc);
        uint2 raw = *(const uint2*)&g_h1h[s * 128 + lane * 4];
        float2 f0 = __half22float2(*(__half2*)&raw.x);
        float2 f1 = __half22float2(*(__half2*)&raw.y);
        a0 += ex * f0.x; a1 += ex * f0.y; a2 += ex * f1.x; a3 += ex * f1.y;
        dsum += ex;
    }
    float inv = 1.f / (dsum + EPSF);
    a0 *= inv; a1 *= inv; a2 *= inv; a3 *= inv;
#pragma unroll
    for (int m = 8; m <= 16; m <<= 1) {
        a0 += __shfl_xor_sync(0xffffffffu, a0, m);
        a1 += __shfl_xor_sync(0xffffffffu, a1, m);
        a2 += __shfl_xor_sync(0xffffffffu, a2, m);
        a3 += __shfl_xor_sync(0xffffffffu, a3, m);
    }
    if (lane < 8) {
        float4 bb = *(const float4*)&b[lane * 4];
        float o0 = 0.25f * a0 + bb.x, o1 = 0.25f * a1 + bb.y;
        float o2 = 0.25f * a2 + bb.z, o3 = 0.25f * a3 + bb.w;
        x2buf[w][lane * 4 + 0] = o0 > 0.f ? o0 : 0.f;
        x2buf[w][lane * 4 + 1] = o1 > 0.f ? o1 : 0.f;
        x2buf[w][lane * 4 + 2] = o2 > 0.f ? o2 : 0.f;
        x2buf[w][lane * 4 + 3] = o3 > 0.f ? o3 : 0.f;
    }
    __syncwarp();
    // gemm2 row: h2[c0], h2[c1] for c0 = lane*2, c1 = lane*2+1
    float h0 = 0.f, h1 = 0.f;
#pragma unroll
    for (int k = 0; k < 32; k++) {
        float xv = x2buf[w][k];      // broadcast
        float2 wv = Ws[k][lane];
        h0 += xv * wv.x;
        h1 += xv * wv.y;
    }
    *(__half2*)&g_h2h[d * 64 + lane * 2] = __floats2half2_rn(h0, h1);
    // attn2
    int c0f = (lane * 2) & 15;
    int h2d = lane >> 3;
    float ps = h0 * a2s[h2d * 16 + c0f] + h1 * a2s[h2d * 16 + c0f + 1];
    float pd = h0 * a2d[h2d * 16 + c0f] + h1 * a2d[h2d * 16 + c0f + 1];
#pragma unroll
    for (int m = 1; m <= 4; m <<= 1) {
        ps += __shfl_xor_sync(0xffffffffu, ps, m);
        pd += __shfl_xor_sync(0xffffffffu, pd, m);
    }
    if ((lane & 7) == 0) {
        g_as2[d * 4 + h2d] = ps;
        g_ad2[d * 4 + h2d] = pd;
    }
}

// ---------------- gather layer 2 (Round-12 form): warp/dst, 2 edge subgroups ----------------
__global__ __launch_bounds__(256) void gather2_kernel(const float* __restrict__ b,
                                                      float* __restrict__ out, int N) {
    int gt = blockIdx.x * 256 + threadIdx.x;
    int d = gt >> 5;
    if (d >= N) return;
    int lane = gt & 31;
    int sub = lane >> 4;      // edge parity
    int l = lane & 15;        // feats l*4..l*4+3
    int head = l >> 2;
    int beg = g_rowptr[d], end = g_rowptr[d + 1];
    float adh = g_ad2[d * 4 + head];
    float a0 = 0.f, a1 = 0.f, a2 = 0.f, a3 = 0.f, dsum = 0.f;
    for (int j = beg + sub; j < end; j += 2) {
        int s = g_csr_src[j];
        float sc = g_as2[s * 4 + head] + adh;
        sc = sc > 0.f ? sc : NEG * sc;
        float ex = __expf(sc);
        uint2 raw = *(const uint2*)&g_h2h[s * 64 + l * 4];
        float2 f0 = __half22float2(*(__half2*)&raw.x);
        float2 f1 = __half22float2(*(__half2*)&raw.y);
        a0 += ex * f0.x; a1 += ex * f0.y; a2 += ex * f1.x; a3 += ex * f1.y;
        dsum += ex;
    }
    // combine edge halves
    a0 += __shfl_xor_sync(0xffffffffu, a0, 16);
    a1 += __shfl_xor_sync(0xffffffffu, a1, 16);
    a2 += __shfl_xor_sync(0xffffffffu, a2, 16);
    a3 += __shfl_xor_sync(0xffffffffu, a3, 16);
    dsum += __shfl_xor_sync(0xffffffffu, dsum, 16);
    float inv = 1.f / (dsum + EPSF);
    a0 *= inv; a1 *= inv; a2 *= inv; a3 *= inv;
    // mean over heads (head bits 2,3 of l)
#pragma unroll
    for (int m = 4; m <= 8; m <<= 1) {
        a0 += __shfl_xor_sync(0xffffffffu, a0, m);
        a1 += __shfl_xor_sync(0xffffffffu, a1, m);
        a2 += __shfl_xor_sync(0xffffffffu, a2, m);
        a3 += __shfl_xor_sync(0xffffffffu, a3, m);
    }
    if (lane < 4) {
        float4 bb = *(const float4*)&b[lane * 4];
        float4 o;
        o.x = 0.25f * a0 + bb.x; o.y = 0.25f * a1 + bb.y;
        o.z = 0.25f * a2 + bb.z; o.w = 0.25f * a3 + bb.w;
        *(float4*)&out[d * 16 + lane * 4] = o;
    }
}

extern "C" void kernel_launch(void* const* d_in, const int* in_sizes, int n_in,
                              void* d_out, int out_size) {
    const float* x = (const float*)d_in[0];
    const void* ei = d_in[1];
    const float* W1 = (const float*)d_in[2];
    const float* a1s = (const float*)d_in[3];
    const float* a1d = (const float*)d_in[4];
    const float* b1 = (const float*)d_in[5];
    const float* W2 = (const float*)d_in[6];
    const float* a2s = (const float*)d_in[7];
    const float* a2d = (const float*)d_in[8];
    const float* b2 = (const float*)d_in[9];
    int N = in_sizes[0] / 128;
    int E = in_sizes[1] / 2;
    if (N > MAXN) N = MAXN;
    if (E > MAXE) E = MAXE;
    float* out = (float*)d_out;
    int nb = (N + 255) / 256;
    int grid_e = (E + 255) / 256;
    int grid_warp = (N * 32 + 255) / 256;
    int grid_g = (N + 63) / 64;

    prep_kernel<<<nb, 256>>>((const int*)ei, W1, N);                 // 1
    decode_count_kernel<<<grid_e, 256>>>(ei, E, N);                  // 2
    scan1_kernel<<<nb, 256>>>(N);                                    // 3
    gemm1_tc_kernel<<<grid_g, 256>>>(x, N);                          // 4  <- ncu samples launch #4
    scan3_kernel<<<nb, 256>>>(N, E, nb);                             // 5
    scatter_kernel<<<grid_e, 256>>>(E);                              // 6
    attn1_kernel<<<(N * 4 + 255) / 256, 256>>>(a1s, a1d, N);         // 7
    gather1_fused_kernel<<<grid_warp, 256>>>(b1, W2, a2s, a2d, N);   // 8
    gather2_kernel<<<grid_warp, 256>>>(b2, out, N);                  // 9
}